// round 12
// baseline (speedup 1.0000x reference)
#include <cuda_runtime.h>
#include <math.h>
#include <cstdint>

#define BB 4
#define SS 2048
#define DM 1024
#define NH 16
#define DK 64
#define MM (BB*SS)   // 8192

// Scratch (allocation-free): __device__ globals
__device__ float g_q[BB*NH*SS*DK];      // [b,h,s,dk]
__device__ float g_k[BB*NH*SS*DK];
__device__ float g_v[BB*NH*SS*DK];
__device__ float g_att[MM*DM];          // [b,s,d] row-major

// ---------------------------------------------------------------------------
// bf16 split helpers: x = hi + lo, hi/lo bf16; packs two values per u32
// (low 16 bits = first element, high 16 bits = second element).
// ---------------------------------------------------------------------------
__device__ __forceinline__ uint32_t pack_bf16x2(float lo_elem, float hi_elem) {
    uint32_t r;
    asm("cvt.rn.bf16x2.f32 %0, %1, %2;" : "=r"(r) : "f"(hi_elem), "f"(lo_elem));
    return r;
}
__device__ __forceinline__ float bf_lo(uint32_t p) { return __uint_as_float(p << 16); }
__device__ __forceinline__ float bf_hi(uint32_t p) { return __uint_as_float(p & 0xffff0000u); }

// split two floats (consecutive k elements) into hi/lo bf16x2 packs
__device__ __forceinline__ void split2(float x, float y, uint32_t& h, uint32_t& l) {
    h = pack_bf16x2(x, y);
    l = pack_bf16x2(x - bf_lo(h), y - bf_hi(h));
}

__device__ __forceinline__ void mma_bf16(float* c, const uint32_t* a, const uint32_t* b) {
    asm volatile(
        "mma.sync.aligned.m16n8k16.row.col.f32.bf16.bf16.f32 "
        "{%0,%1,%2,%3}, {%4,%5,%6,%7}, {%8,%9}, {%0,%1,%2,%3};"
        : "+f"(c[0]), "+f"(c[1]), "+f"(c[2]), "+f"(c[3])
        : "r"(a[0]), "r"(a[1]), "r"(a[2]), "r"(a[3]), "r"(b[0]), "r"(b[1]));
}

// ===========================================================================
// Split-bf16 tensor-core GEMM: C = A @ W^T (3-term: AhBh + AhBl + AlBh).
// A:[M,1024], W:[1024,1024] row-major. Block 128x128, BK=32, 256 thr,
// warp grid 4m x 2n, warp tile 32x64. Smem holds bf16x2 K-pairs, pitch 20.
// ===========================================================================
#define GP 20   // 16 data u32 + 4 pad: frag bank = (20*gid+tig)%32, bijective

__global__ __launch_bounds__(256) void tgemm_kernel(const float* __restrict__ A,
                                                    const float* __restrict__ W,
                                                    float* __restrict__ C,
                                                    int scatter)
{
    __shared__ uint32_t Ah[128 * GP], Al[128 * GP];
    __shared__ uint32_t Bh[128 * GP], Bl[128 * GP];

    const int tid = threadIdx.x;
    const int wid = tid >> 5, lid = tid & 31;
    const int gid = lid >> 2, tig = lid & 3;
    const int wm = (wid & 3) * 32;
    const int wn = (wid >> 2) * 64;
    const int m0 = blockIdx.y * 128, n0 = blockIdx.x * 128;

    const int ldrow = tid >> 3;
    const int ldc4  = tid & 7;     // float4 chunk -> pairs 2*ldc4, 2*ldc4+1

    float acc[2][8][4] = {};
    float4 pa[4], pb[4];

#pragma unroll
    for (int i = 0; i < 4; i++) {
        int row = ldrow + i * 32;
        pa[i] = *(const float4*)(A + (size_t)(m0 + row) * DM + ldc4 * 4);
        pb[i] = *(const float4*)(W + (size_t)(n0 + row) * DM + ldc4 * 4);
    }

    for (int it = 0; it < DM / 32; ++it) {
#pragma unroll
        for (int i = 0; i < 4; i++) {
            int row = ldrow + i * 32;
            uint32_t off = row * GP + ldc4 * 2;
            uint32_t h0, l0, h1, l1;
            split2(pa[i].x, pa[i].y, h0, l0);
            split2(pa[i].z, pa[i].w, h1, l1);
            Ah[off] = h0; Ah[off + 1] = h1;
            Al[off] = l0; Al[off + 1] = l1;
            split2(pb[i].x, pb[i].y, h0, l0);
            split2(pb[i].z, pb[i].w, h1, l1);
            Bh[off] = h0; Bh[off + 1] = h1;
            Bl[off] = l0; Bl[off + 1] = l1;
        }
        __syncthreads();

        if (it + 1 < DM / 32) {
            int kk = (it + 1) * 32;
#pragma unroll
            for (int i = 0; i < 4; i++) {
                int row = ldrow + i * 32;
                pa[i] = *(const float4*)(A + (size_t)(m0 + row) * DM + kk + ldc4 * 4);
                pb[i] = *(const float4*)(W + (size_t)(n0 + row) * DM + kk + ldc4 * 4);
            }
        }

        // 2 k-steps of 16
#pragma unroll
        for (int ks = 0; ks < 2; ks++) {
            const int c0 = ks * 8;    // pair index base
            uint32_t ah[2][4], al[2][4], bh[8][2], bl[8][2];
#pragma unroll
            for (int mt = 0; mt < 2; mt++) {
                int r = wm + mt * 16 + gid;
                ah[mt][0] = Ah[r * GP + c0 + tig];
                ah[mt][1] = Ah[(r + 8) * GP + c0 + tig];
                ah[mt][2] = Ah[r * GP + c0 + tig + 4];
                ah[mt][3] = Ah[(r + 8) * GP + c0 + tig + 4];
                al[mt][0] = Al[r * GP + c0 + tig];
                al[mt][1] = Al[(r + 8) * GP + c0 + tig];
                al[mt][2] = Al[r * GP + c0 + tig + 4];
                al[mt][3] = Al[(r + 8) * GP + c0 + tig + 4];
            }
#pragma unroll
            for (int nt = 0; nt < 8; nt++) {
                int cn = wn + nt * 8 + gid;
                bh[nt][0] = Bh[cn * GP + c0 + tig];
                bh[nt][1] = Bh[cn * GP + c0 + tig + 4];
                bl[nt][0] = Bl[cn * GP + c0 + tig];
                bl[nt][1] = Bl[cn * GP + c0 + tig + 4];
            }
#pragma unroll
            for (int mt = 0; mt < 2; mt++)
#pragma unroll
                for (int nt = 0; nt < 8; nt++) {
                    mma_bf16(acc[mt][nt], ah[mt], bh[nt]);
                    mma_bf16(acc[mt][nt], ah[mt], bl[nt]);
                    mma_bf16(acc[mt][nt], al[mt], bh[nt]);
                }
        }
        __syncthreads();
    }

    // epilogue (same C layout as before)
#pragma unroll
    for (int mt = 0; mt < 2; mt++) {
#pragma unroll
        for (int nt = 0; nt < 8; nt++) {
            int m = m0 + wm + mt * 16 + gid;
            int n = n0 + wn + nt * 8 + 2 * tig;
            float2 lo = make_float2(acc[mt][nt][0], acc[mt][nt][1]);
            float2 hi = make_float2(acc[mt][nt][2], acc[mt][nt][3]);
            if (scatter) {
                int h = n >> 6, d = n & 63;
                int b1 = m >> 11, s1 = m & 2047;
                int m2 = m + 8;
                int b2 = m2 >> 11, s2 = m2 & 2047;
                *(float2*)(C + (((size_t)((b1 << 4) + h)) * SS + s1) * DK + d) = lo;
                *(float2*)(C + (((size_t)((b2 << 4) + h)) * SS + s2) * DK + d) = hi;
            } else {
                *(float2*)(C + (size_t)m * DM + n) = lo;
                *(float2*)(C + (size_t)(m + 8) * DM + n) = hi;
            }
        }
    }
}

// ---------------------------------------------------------------------------
// RoPE in-place on [bh, s, dk] tensor.
// ---------------------------------------------------------------------------
__global__ void rope_kernel(float* __restrict__ X)
{
    int idx = blockIdx.x * 256 + threadIdx.x;
    int i  = idx & 31;
    int s  = (idx >> 5) & 2047;
    int bh = idx >> 16;
    float inv = powf(10000.0f, -(2.0f * (float)i) / 64.0f);
    float ang = (float)s * inv;
    float sn, cs;
    sincosf(ang, &sn, &cs);
    float* p = X + ((size_t)bh * SS + s) * DK + 2 * i;
    float x1 = p[0], x2 = p[1];
    p[0] = x1 * cs - x2 * sn;
    p[1] = x1 * sn + x2 * cs;
}

// ===========================================================================
// Split-bf16 causal flash attention (3-term, fp32-grade).
// Grid: (32 qtiles, 64 bh). Block 128 = 4 warps x 16 q-rows.
// K staged as bf16x2 dk-pairs [kv][32], pitch 36.
// V staged TRANSPOSED as bf16x2 kv-pairs [d][16], pitch 20.
// S C-frag == PV A-frag for m16n8k16 -> zero shuffles.
// ===========================================================================
#define KP2 36   // Ks pitch: frag bank = (4*gid+tig), bijective
#define VTP 20   // Vt pitch: frag bank = (20*gid+tig)%32, bijective

__global__ __launch_bounds__(128) void fattn_kernel(const float* __restrict__ Q,
                                                    const float* __restrict__ K,
                                                    const float* __restrict__ V,
                                                    float* __restrict__ O)
{
    __shared__ uint32_t Kh[32 * KP2], Kl[32 * KP2];
    __shared__ uint32_t Vth[64 * VTP], Vtl[64 * VTP];

    const int tid = threadIdx.x, wid = tid >> 5, lid = tid & 31;
    const int gid = lid >> 2, tig = lid & 3;
    const int qt = 31 - blockIdx.x;          // heavy tiles first
    const int bh = blockIdx.y;
    const int h = bh & 15, b = bh >> 4;
    const int wrow = qt * 64 + wid * 16 + gid;

    const float* Qb = Q + (size_t)bh * SS * DK;
    const float* Kb = K + (size_t)bh * SS * DK;
    const float* Vb = V + (size_t)bh * SS * DK;

    // Hoist Q A-fragments (hi/lo) for 4 k16-steps
    uint32_t qh[4][4], ql[4][4];
    {
        const float* r0 = Qb + (size_t)wrow * DK;
        const float* r1 = r0 + 8 * DK;
#pragma unroll
        for (int ks = 0; ks < 4; ks++) {
            int d0 = ks * 16 + 2 * tig;
            float2 x0 = *(const float2*)(r0 + d0);      // a0: row, k 2tig..+1
            float2 x1 = *(const float2*)(r1 + d0);      // a1: row+8
            float2 x2 = *(const float2*)(r0 + d0 + 8);  // a2: row, k 2tig+8..+9
            float2 x3 = *(const float2*)(r1 + d0 + 8);  // a3: row+8
            split2(x0.x, x0.y, qh[ks][0], ql[ks][0]);
            split2(x1.x, x1.y, qh[ks][1], ql[ks][1]);
            split2(x2.x, x2.y, qh[ks][2], ql[ks][2]);
            split2(x3.x, x3.y, qh[ks][3], ql[ks][3]);
        }
    }

    float oacc[8][4] = {};
    float m0 = -1e30f, m1 = -1e30f, l0 = 0.0f, l1 = 0.0f;

    const int ntiles = 2 * qt + 2;
    for (int t = 0; t < ntiles; t++) {
        const int kv0 = t * 32;
        const bool domask = (t >= 2 * qt);
        __syncthreads();

        // Stage K tile: [32 kv][64 dk] -> bf16x2 dk-pairs
#pragma unroll
        for (int j = 0; j < 4; j++) {
            int id = tid + j * 128;         // 0..511
            int kv = id >> 4, c = id & 15;  // c: float4 chunk (d = 4c)
            float4 kf = *(const float4*)(Kb + (size_t)(kv0 + kv) * DK + c * 4);
            uint32_t h0, L0, h1, L1;
            split2(kf.x, kf.y, h0, L0);
            split2(kf.z, kf.w, h1, L1);
            uint32_t off = kv * KP2 + 2 * c;
            Kh[off] = h0; Kh[off + 1] = h1;
            Kl[off] = L0; Kl[off + 1] = L1;
        }
        // Stage V tile TRANSPOSED: pairs along kv -> Vt[d][kv/2]
#pragma unroll
        for (int j = 0; j < 2; j++) {
            int id = tid + j * 128;         // 0..255
            int p = id & 15, c = id >> 4;   // p: kv pair, c: d chunk
            float4 v0 = *(const float4*)(Vb + (size_t)(kv0 + 2 * p) * DK + c * 4);
            float4 v1 = *(const float4*)(Vb + (size_t)(kv0 + 2 * p + 1) * DK + c * 4);
            float e0[4] = {v0.x, v0.y, v0.z, v0.w};
            float e1[4] = {v1.x, v1.y, v1.z, v1.w};
#pragma unroll
            for (int e = 0; e < 4; e++) {
                uint32_t hh, ll;
                split2(e0[e], e1[e], hh, ll);
                Vth[(4 * c + e) * VTP + p] = hh;
                Vtl[(4 * c + e) * VTP + p] = ll;
            }
        }
        __syncthreads();

        // ---- S = Q K^T (3-term split-bf16) ----
        float sfr[4][4] = {};
#pragma unroll
        for (int ks = 0; ks < 4; ks++) {
#pragma unroll
            for (int nt = 0; nt < 4; nt++) {
                int base = (nt * 8 + gid) * KP2 + ks * 8 + tig;
                uint32_t BH[2] = { Kh[base], Kh[base + 4] };
                uint32_t BL[2] = { Kl[base], Kl[base + 4] };
                mma_bf16(sfr[nt], qh[ks], BH);
                mma_bf16(sfr[nt], qh[ks], BL);
                mma_bf16(sfr[nt], ql[ks], BH);
            }
        }

        // ---- scale + mask + online softmax ----
        float tm0 = -1e30f, tm1 = -1e30f;
#pragma unroll
        for (int nt = 0; nt < 4; nt++) {
            int c = kv0 + nt * 8 + 2 * tig;
            float v0 = sfr[nt][0] * 0.125f;
            float v1 = sfr[nt][1] * 0.125f;
            float v2 = sfr[nt][2] * 0.125f;
            float v3 = sfr[nt][3] * 0.125f;
            if (domask) {
                if (c     > wrow)     v0 = -1e30f;
                if (c + 1 > wrow)     v1 = -1e30f;
                if (c     > wrow + 8) v2 = -1e30f;
                if (c + 1 > wrow + 8) v3 = -1e30f;
            }
            sfr[nt][0] = v0; sfr[nt][1] = v1; sfr[nt][2] = v2; sfr[nt][3] = v3;
            tm0 = fmaxf(tm0, fmaxf(v0, v1));
            tm1 = fmaxf(tm1, fmaxf(v2, v3));
        }
        tm0 = fmaxf(tm0, __shfl_xor_sync(0xffffffffu, tm0, 1));
        tm0 = fmaxf(tm0, __shfl_xor_sync(0xffffffffu, tm0, 2));
        tm1 = fmaxf(tm1, __shfl_xor_sync(0xffffffffu, tm1, 1));
        tm1 = fmaxf(tm1, __shfl_xor_sync(0xffffffffu, tm1, 2));

        float mn0 = fmaxf(m0, tm0), mn1 = fmaxf(m1, tm1);
        float a0 = __expf(m0 - mn0), a1 = __expf(m1 - mn1);
        float s0 = 0.0f, s1 = 0.0f;
#pragma unroll
        for (int nt = 0; nt < 4; nt++) {
            float p0 = __expf(sfr[nt][0] - mn0);
            float p1 = __expf(sfr[nt][1] - mn0);
            float p2 = __expf(sfr[nt][2] - mn1);
            float p3 = __expf(sfr[nt][3] - mn1);
            sfr[nt][0] = p0; sfr[nt][1] = p1; sfr[nt][2] = p2; sfr[nt][3] = p3;
            s0 += p0 + p1; s1 += p2 + p3;
        }
        s0 += __shfl_xor_sync(0xffffffffu, s0, 1);
        s0 += __shfl_xor_sync(0xffffffffu, s0, 2);
        s1 += __shfl_xor_sync(0xffffffffu, s1, 1);
        s1 += __shfl_xor_sync(0xffffffffu, s1, 2);
        l0 = l0 * a0 + s0; l1 = l1 * a1 + s1;
        m0 = mn0; m1 = mn1;
#pragma unroll
        for (int nt = 0; nt < 8; nt++) {
            oacc[nt][0] *= a0; oacc[nt][1] *= a0;
            oacc[nt][2] *= a1; oacc[nt][3] *= a1;
        }

        // ---- O += P V (3-term split-bf16): S C-frag IS the PV A-frag ----
#pragma unroll
        for (int Ks = 0; Ks < 2; Ks++) {
            uint32_t ph[4], pl[4];
            split2(sfr[2*Ks][0],     sfr[2*Ks][1],     ph[0], pl[0]);  // a0: row gid,   k 2tig..+1
            split2(sfr[2*Ks][2],     sfr[2*Ks][3],     ph[1], pl[1]);  // a1: row gid+8
            split2(sfr[2*Ks + 1][0], sfr[2*Ks + 1][1], ph[2], pl[2]);  // a2: row gid,   k 2tig+8..+9
            split2(sfr[2*Ks + 1][2], sfr[2*Ks + 1][3], ph[3], pl[3]);  // a3: row gid+8
#pragma unroll
            for (int nt = 0; nt < 8; nt++) {
                int base = (nt * 8 + gid) * VTP + Ks * 8 + tig;
                uint32_t BH[2] = { Vth[base], Vth[base + 4] };
                uint32_t BL[2] = { Vtl[base], Vtl[base + 4] };
                mma_bf16(oacc[nt], ph, BH);
                mma_bf16(oacc[nt], ph, BL);
                mma_bf16(oacc[nt], pl, BH);
            }
        }
    }

    // ---- epilogue ----
    float i0 = 1.0f / l0, i1 = 1.0f / l1;
    float* o0 = O + ((size_t)b * SS + wrow) * DM + h * 64;
    float* o1 = o0 + 8 * DM;
#pragma unroll
    for (int nt = 0; nt < 8; nt++) {
        *(float2*)(o0 + nt * 8 + 2 * tig) =
            make_float2(oacc[nt][0] * i0, oacc[nt][1] * i0);
        *(float2*)(o1 + nt * 8 + 2 * tig) =
            make_float2(oacc[nt][2] * i1, oacc[nt][3] * i1);
    }
}

// ---------------------------------------------------------------------------
extern "C" void kernel_launch(void* const* d_in, const int* in_sizes, int n_in,
                              void* d_out, int out_size)
{
    const float* x  = (const float*)d_in[0];
    const float* qw = (const float*)d_in[1];
    const float* kw = (const float*)d_in[2];
    const float* vw = (const float*)d_in[3];
    const float* ow = (const float*)d_in[4];
    float* out = (float*)d_out;

    float *q, *k, *v, *att;
    cudaGetSymbolAddress((void**)&q,   g_q);
    cudaGetSymbolAddress((void**)&k,   g_k);
    cudaGetSymbolAddress((void**)&v,   g_v);
    cudaGetSymbolAddress((void**)&att, g_att);

    dim3 gg(DM / 128, MM / 128);   // (8, 64) = 512 CTAs

    tgemm_kernel<<<gg, 256>>>(x, qw, q, 1);
    tgemm_kernel<<<gg, 256>>>(x, kw, k, 1);
    tgemm_kernel<<<gg, 256>>>(x, vw, v, 1);

    const int nrope = BB * NH * SS * 32;
    rope_kernel<<<nrope / 256, 256>>>(q);
    rope_kernel<<<nrope / 256, 256>>>(k);

    fattn_kernel<<<dim3(32, 64), 128>>>(q, k, v, att);

    tgemm_kernel<<<gg, 256>>>(att, ow, out, 0);
}

// round 14
// speedup vs baseline: 1.1960x; 1.1960x over previous
#include <cuda_runtime.h>
#include <math.h>
#include <cstdint>

#define BB 4
#define SS 2048
#define DM 1024
#define NH 16
#define DK 64
#define MM (BB*SS)   // 8192

// Scratch (allocation-free): __device__ globals
__device__ float g_q[BB*NH*SS*DK];      // [b,h,s,dk]
__device__ float g_k[BB*NH*SS*DK];
__device__ float g_v[BB*NH*SS*DK];
__device__ float g_att[MM*DM];          // [b,s,d] row-major

// ---------------------------------------------------------------------------
// tf32 + bf16 helpers
// ---------------------------------------------------------------------------
__device__ __forceinline__ uint32_t f2tf32(float f) {
    uint32_t r;
    asm("cvt.rna.tf32.f32 %0, %1;" : "=r"(r) : "f"(f));
    return r;
}
__device__ __forceinline__ void mma_tf32(float* c, const uint32_t* a, const uint32_t* b) {
    asm volatile(
        "mma.sync.aligned.m16n8k8.row.col.f32.tf32.tf32.f32 "
        "{%0,%1,%2,%3}, {%4,%5,%6,%7}, {%8,%9}, {%0,%1,%2,%3};"
        : "+f"(c[0]), "+f"(c[1]), "+f"(c[2]), "+f"(c[3])
        : "r"(a[0]), "r"(a[1]), "r"(a[2]), "r"(a[3]), "r"(b[0]), "r"(b[1]));
}

__device__ __forceinline__ uint32_t pack_bf16x2(float lo_elem, float hi_elem) {
    uint32_t r;
    asm("cvt.rn.bf16x2.f32 %0, %1, %2;" : "=r"(r) : "f"(hi_elem), "f"(lo_elem));
    return r;
}
__device__ __forceinline__ float bf_lo(uint32_t p) { return __uint_as_float(p << 16); }
__device__ __forceinline__ float bf_hi(uint32_t p) { return __uint_as_float(p & 0xffff0000u); }
__device__ __forceinline__ void split2(float x, float y, uint32_t& h, uint32_t& l) {
    h = pack_bf16x2(x, y);
    l = pack_bf16x2(x - bf_lo(h), y - bf_hi(h));
}
__device__ __forceinline__ void mma_bf16(float* c, const uint32_t* a, const uint32_t* b) {
    asm volatile(
        "mma.sync.aligned.m16n8k16.row.col.f32.bf16.bf16.f32 "
        "{%0,%1,%2,%3}, {%4,%5,%6,%7}, {%8,%9}, {%0,%1,%2,%3};"
        : "+f"(c[0]), "+f"(c[1]), "+f"(c[2]), "+f"(c[3])
        : "r"(a[0]), "r"(a[1]), "r"(a[2]), "r"(a[3]), "r"(b[0]), "r"(b[1]));
}

// ===========================================================================
// Plain-tf32 tensor-core GEMM (R11, measured ~130us each): C = A @ W^T.
// Block 128x128, BK=32, 256 thr, warp grid 4m x 2n, warp tile 32x64.
// ===========================================================================
#define SPITCH 36

__global__ __launch_bounds__(256) void tgemm_kernel(const float* __restrict__ A,
                                                    const float* __restrict__ W,
                                                    float* __restrict__ C,
                                                    int scatter)
{
    __shared__ uint32_t As[128 * SPITCH];
    __shared__ uint32_t Bs[128 * SPITCH];

    const int tid = threadIdx.x;
    const int wid = tid >> 5, lid = tid & 31;
    const int gid = lid >> 2, tig = lid & 3;
    const int wm = (wid & 3) * 32;
    const int wn = (wid >> 2) * 64;
    const int m0 = blockIdx.y * 128, n0 = blockIdx.x * 128;

    const int ldrow = tid >> 3;
    const int ldc4  = tid & 7;

    float acc[2][8][4] = {};
    float4 pa[4], pb[4];

#pragma unroll
    for (int i = 0; i < 4; i++) {
        int row = ldrow + i * 32;
        pa[i] = *(const float4*)(A + (size_t)(m0 + row) * DM + ldc4 * 4);
        pb[i] = *(const float4*)(W + (size_t)(n0 + row) * DM + ldc4 * 4);
    }

    for (int it = 0; it < DM / 32; ++it) {
#pragma unroll
        for (int i = 0; i < 4; i++) {
            int row = ldrow + i * 32;
            uint32_t off = row * SPITCH + ldc4 * 4;
            As[off+0] = f2tf32(pa[i].x); As[off+1] = f2tf32(pa[i].y);
            As[off+2] = f2tf32(pa[i].z); As[off+3] = f2tf32(pa[i].w);
            Bs[off+0] = f2tf32(pb[i].x); Bs[off+1] = f2tf32(pb[i].y);
            Bs[off+2] = f2tf32(pb[i].z); Bs[off+3] = f2tf32(pb[i].w);
        }
        __syncthreads();

        if (it + 1 < DM / 32) {
            int kk = (it + 1) * 32;
#pragma unroll
            for (int i = 0; i < 4; i++) {
                int row = ldrow + i * 32;
                pa[i] = *(const float4*)(A + (size_t)(m0 + row) * DM + kk + ldc4 * 4);
                pb[i] = *(const float4*)(W + (size_t)(n0 + row) * DM + kk + ldc4 * 4);
            }
        }

#pragma unroll
        for (int ks = 0; ks < 4; ks++) {
            const int k0 = ks * 8;
            uint32_t a[2][4], b[8][2];
#pragma unroll
            for (int mt = 0; mt < 2; mt++) {
                int r = wm + mt * 16 + gid;
                a[mt][0] = As[r * SPITCH + k0 + tig];
                a[mt][1] = As[(r + 8) * SPITCH + k0 + tig];
                a[mt][2] = As[r * SPITCH + k0 + tig + 4];
                a[mt][3] = As[(r + 8) * SPITCH + k0 + tig + 4];
            }
#pragma unroll
            for (int nt = 0; nt < 8; nt++) {
                int cn = wn + nt * 8 + gid;
                b[nt][0] = Bs[cn * SPITCH + k0 + tig];
                b[nt][1] = Bs[cn * SPITCH + k0 + tig + 4];
            }
#pragma unroll
            for (int mt = 0; mt < 2; mt++)
#pragma unroll
                for (int nt = 0; nt < 8; nt++)
                    mma_tf32(acc[mt][nt], a[mt], b[nt]);
        }
        __syncthreads();
    }

#pragma unroll
    for (int mt = 0; mt < 2; mt++) {
#pragma unroll
        for (int nt = 0; nt < 8; nt++) {
            int m = m0 + wm + mt * 16 + gid;
            int n = n0 + wn + nt * 8 + 2 * tig;
            float2 lo = make_float2(acc[mt][nt][0], acc[mt][nt][1]);
            float2 hi = make_float2(acc[mt][nt][2], acc[mt][nt][3]);
            if (scatter) {
                int h = n >> 6, d = n & 63;
                int b1 = m >> 11, s1 = m & 2047;
                int m2 = m + 8;
                int b2 = m2 >> 11, s2 = m2 & 2047;
                *(float2*)(C + (((size_t)((b1 << 4) + h)) * SS + s1) * DK + d) = lo;
                *(float2*)(C + (((size_t)((b2 << 4) + h)) * SS + s2) * DK + d) = hi;
            } else {
                *(float2*)(C + (size_t)m * DM + n) = lo;
                *(float2*)(C + (size_t)(m + 8) * DM + n) = hi;
            }
        }
    }
}

// ---------------------------------------------------------------------------
// RoPE in-place on [bh, s, dk] tensor.
// ---------------------------------------------------------------------------
__global__ void rope_kernel(float* __restrict__ X)
{
    int idx = blockIdx.x * 256 + threadIdx.x;
    int i  = idx & 31;
    int s  = (idx >> 5) & 2047;
    int bh = idx >> 16;
    float inv = powf(10000.0f, -(2.0f * (float)i) / 64.0f);
    float ang = (float)s * inv;
    float sn, cs;
    sincosf(ang, &sn, &cs);
    float* p = X + ((size_t)bh * SS + s) * DK + 2 * i;
    float x1 = p[0], x2 = p[1];
    p[0] = x1 * cs - x2 * sn;
    p[1] = x1 * sn + x2 * cs;
}

// ===========================================================================
// Split-bf16 causal flash attention (R12, measured; 3-term, fp32-grade).
// Grid: (32 qtiles, 64 bh). Block 128 = 4 warps x 16 q-rows.
// S C-frag == PV A-frag for m16n8k16 -> zero shuffles.
// ===========================================================================
#define KP2 36   // Ks pitch: frag bank = (4*gid+tig), bijective
#define VTP 20   // Vt pitch: frag bank = (20*gid+tig)%32, bijective

__global__ __launch_bounds__(128) void fattn_kernel(const float* __restrict__ Q,
                                                    const float* __restrict__ K,
                                                    const float* __restrict__ V,
                                                    float* __restrict__ O)
{
    __shared__ uint32_t Kh[32 * KP2], Kl[32 * KP2];
    __shared__ uint32_t Vth[64 * VTP], Vtl[64 * VTP];

    const int tid = threadIdx.x, wid = tid >> 5, lid = tid & 31;
    const int gid = lid >> 2, tig = lid & 3;
    const int qt = 31 - blockIdx.x;          // heavy tiles first
    const int bh = blockIdx.y;
    const int h = bh & 15, b = bh >> 4;
    const int wrow = qt * 64 + wid * 16 + gid;

    const float* Qb = Q + (size_t)bh * SS * DK;
    const float* Kb = K + (size_t)bh * SS * DK;
    const float* Vb = V + (size_t)bh * SS * DK;

    // Hoist Q A-fragments (hi/lo) for 4 k16-steps
    uint32_t qh[4][4], ql[4][4];
    {
        const float* r0 = Qb + (size_t)wrow * DK;
        const float* r1 = r0 + 8 * DK;
#pragma unroll
        for (int ks = 0; ks < 4; ks++) {
            int d0 = ks * 16 + 2 * tig;
            float2 x0 = *(const float2*)(r0 + d0);
            float2 x1 = *(const float2*)(r1 + d0);
            float2 x2 = *(const float2*)(r0 + d0 + 8);
            float2 x3 = *(const float2*)(r1 + d0 + 8);
            split2(x0.x, x0.y, qh[ks][0], ql[ks][0]);
            split2(x1.x, x1.y, qh[ks][1], ql[ks][1]);
            split2(x2.x, x2.y, qh[ks][2], ql[ks][2]);
            split2(x3.x, x3.y, qh[ks][3], ql[ks][3]);
        }
    }

    float oacc[8][4] = {};
    float m0 = -1e30f, m1 = -1e30f, l0 = 0.0f, l1 = 0.0f;

    const int ntiles = 2 * qt + 2;
    for (int t = 0; t < ntiles; t++) {
        const int kv0 = t * 32;
        const bool domask = (t >= 2 * qt);
        __syncthreads();

        // Stage K tile: [32 kv][64 dk] -> bf16x2 dk-pairs
#pragma unroll
        for (int j = 0; j < 4; j++) {
            int id = tid + j * 128;
            int kv = id >> 4, c = id & 15;
            float4 kf = *(const float4*)(Kb + (size_t)(kv0 + kv) * DK + c * 4);
            uint32_t h0, L0, h1, L1;
            split2(kf.x, kf.y, h0, L0);
            split2(kf.z, kf.w, h1, L1);
            uint32_t off = kv * KP2 + 2 * c;
            Kh[off] = h0; Kh[off + 1] = h1;
            Kl[off] = L0; Kl[off + 1] = L1;
        }
        // Stage V tile TRANSPOSED: pairs along kv -> Vt[d][kv/2]
#pragma unroll
        for (int j = 0; j < 2; j++) {
            int id = tid + j * 128;
            int p = id & 15, c = id >> 4;
            float4 v0 = *(const float4*)(Vb + (size_t)(kv0 + 2 * p) * DK + c * 4);
            float4 v1 = *(const float4*)(Vb + (size_t)(kv0 + 2 * p + 1) * DK + c * 4);
            float e0[4] = {v0.x, v0.y, v0.z, v0.w};
            float e1[4] = {v1.x, v1.y, v1.z, v1.w};
#pragma unroll
            for (int e = 0; e < 4; e++) {
                uint32_t hh, ll;
                split2(e0[e], e1[e], hh, ll);
                Vth[(4 * c + e) * VTP + p] = hh;
                Vtl[(4 * c + e) * VTP + p] = ll;
            }
        }
        __syncthreads();

        // ---- S = Q K^T (3-term split-bf16) ----
        float sfr[4][4] = {};
#pragma unroll
        for (int ks = 0; ks < 4; ks++) {
#pragma unroll
            for (int nt = 0; nt < 4; nt++) {
                int base = (nt * 8 + gid) * KP2 + ks * 8 + tig;
                uint32_t BH[2] = { Kh[base], Kh[base + 4] };
                uint32_t BL[2] = { Kl[base], Kl[base + 4] };
                mma_bf16(sfr[nt], qh[ks], BH);
                mma_bf16(sfr[nt], qh[ks], BL);
                mma_bf16(sfr[nt], ql[ks], BH);
            }
        }

        // ---- scale + mask + online softmax ----
        float tm0 = -1e30f, tm1 = -1e30f;
#pragma unroll
        for (int nt = 0; nt < 4; nt++) {
            int c = kv0 + nt * 8 + 2 * tig;
            float v0 = sfr[nt][0] * 0.125f;
            float v1 = sfr[nt][1] * 0.125f;
            float v2 = sfr[nt][2] * 0.125f;
            float v3 = sfr[nt][3] * 0.125f;
            if (domask) {
                if (c     > wrow)     v0 = -1e30f;
                if (c + 1 > wrow)     v1 = -1e30f;
                if (c     > wrow + 8) v2 = -1e30f;
                if (c + 1 > wrow + 8) v3 = -1e30f;
            }
            sfr[nt][0] = v0; sfr[nt][1] = v1; sfr[nt][2] = v2; sfr[nt][3] = v3;
            tm0 = fmaxf(tm0, fmaxf(v0, v1));
            tm1 = fmaxf(tm1, fmaxf(v2, v3));
        }
        tm0 = fmaxf(tm0, __shfl_xor_sync(0xffffffffu, tm0, 1));
        tm0 = fmaxf(tm0, __shfl_xor_sync(0xffffffffu, tm0, 2));
        tm1 = fmaxf(tm1, __shfl_xor_sync(0xffffffffu, tm1, 1));
        tm1 = fmaxf(tm1, __shfl_xor_sync(0xffffffffu, tm1, 2));

        float mn0 = fmaxf(m0, tm0), mn1 = fmaxf(m1, tm1);
        float a0 = __expf(m0 - mn0), a1 = __expf(m1 - mn1);
        float s0 = 0.0f, s1 = 0.0f;
#pragma unroll
        for (int nt = 0; nt < 4; nt++) {
            float p0 = __expf(sfr[nt][0] - mn0);
            float p1 = __expf(sfr[nt][1] - mn0);
            float p2 = __expf(sfr[nt][2] - mn1);
            float p3 = __expf(sfr[nt][3] - mn1);
            sfr[nt][0] = p0; sfr[nt][1] = p1; sfr[nt][2] = p2; sfr[nt][3] = p3;
            s0 += p0 + p1; s1 += p2 + p3;
        }
        s0 += __shfl_xor_sync(0xffffffffu, s0, 1);
        s0 += __shfl_xor_sync(0xffffffffu, s0, 2);
        s1 += __shfl_xor_sync(0xffffffffu, s1, 1);
        s1 += __shfl_xor_sync(0xffffffffu, s1, 2);
        l0 = l0 * a0 + s0; l1 = l1 * a1 + s1;
        m0 = mn0; m1 = mn1;
#pragma unroll
        for (int nt = 0; nt < 8; nt++) {
            oacc[nt][0] *= a0; oacc[nt][1] *= a0;
            oacc[nt][2] *= a1; oacc[nt][3] *= a1;
        }

        // ---- O += P V (3-term split-bf16): S C-frag IS the PV A-frag ----
#pragma unroll
        for (int Ks = 0; Ks < 2; Ks++) {
            uint32_t ph[4], pl[4];
            split2(sfr[2*Ks][0],     sfr[2*Ks][1],     ph[0], pl[0]);
            split2(sfr[2*Ks][2],     sfr[2*Ks][3],     ph[1], pl[1]);
            split2(sfr[2*Ks + 1][0], sfr[2*Ks + 1][1], ph[2], pl[2]);
            split2(sfr[2*Ks + 1][2], sfr[2*Ks + 1][3], ph[3], pl[3]);
#pragma unroll
            for (int nt = 0; nt < 8; nt++) {
                int base = (nt * 8 + gid) * VTP + Ks * 8 + tig;
                uint32_t BH[2] = { Vth[base], Vth[base + 4] };
                uint32_t BL[2] = { Vtl[base], Vtl[base + 4] };
                mma_bf16(oacc[nt], ph, BH);
                mma_bf16(oacc[nt], ph, BL);
                mma_bf16(oacc[nt], pl, BH);
            }
        }
    }

    // ---- epilogue ----
    float i0 = 1.0f / l0, i1 = 1.0f / l1;
    float* o0 = O + ((size_t)b * SS + wrow) * DM + h * 64;
    float* o1 = o0 + 8 * DM;
#pragma unroll
    for (int nt = 0; nt < 8; nt++) {
        *(float2*)(o0 + nt * 8 + 2 * tig) =
            make_float2(oacc[nt][0] * i0, oacc[nt][1] * i0);
        *(float2*)(o1 + nt * 8 + 2 * tig) =
            make_float2(oacc[nt][2] * i1, oacc[nt][3] * i1);
    }
}

// ---------------------------------------------------------------------------
extern "C" void kernel_launch(void* const* d_in, const int* in_sizes, int n_in,
                              void* d_out, int out_size)
{
    const float* x  = (const float*)d_in[0];
    const float* qw = (const float*)d_in[1];
    const float* kw = (const float*)d_in[2];
    const float* vw = (const float*)d_in[3];
    const float* ow = (const float*)d_in[4];
    float* out = (float*)d_out;

    float *q, *k, *v, *att;
    cudaGetSymbolAddress((void**)&q,   g_q);
    cudaGetSymbolAddress((void**)&k,   g_k);
    cudaGetSymbolAddress((void**)&v,   g_v);
    cudaGetSymbolAddress((void**)&att, g_att);

    dim3 gg(DM / 128, MM / 128);   // (8, 64) = 512 CTAs

    tgemm_kernel<<<gg, 256>>>(x, qw, q, 1);
    tgemm_kernel<<<gg, 256>>>(x, kw, k, 1);
    tgemm_kernel<<<gg, 256>>>(x, vw, v, 1);

    const int nrope = BB * NH * SS * 32;
    rope_kernel<<<nrope / 256, 256>>>(q);
    rope_kernel<<<nrope / 256, 256>>>(k);

    fattn_kernel<<<dim3(32, 64), 128>>>(q, k, v, att);

    tgemm_kernel<<<gg, 256>>>(att, ow, out, 0);
}